// round 6
// baseline (speedup 1.0000x reference)
#include <cuda_runtime.h>

// WordEmbeddingModule: B=32768 words, LMAX=24, M=10, D=300, V=36.
// out[b, m, :] =
//   L <  M, m <  L : emb_table[tokens[b,m]]
//   L <  M, m >= L : pad_table[0]
//   L >= M         : lerp(emb[tok[lo]], emb[tok[hi]], w),
//                    pos = m*(L-1)/(M-1), lo=floor(pos), hi=min(lo+1,L-1), w=pos-lo
//
// HBM-store-bound: 393 MB out @ 6.86 TB/s (R2) ~ 86% of spec. R3: coarsen to
// 480-thread CTAs x 16 words => exactly 25 uniform iterations/thread (no tail,
// no predication), 16x fewer CTAs/syncs. Metadata packed one float4 per row.

#define B_WORDS 32768
#define LMAX    24
#define M_OUT   10
#define D_VEC   75                        // 300 floats / 4
#define WORDS_PER_CTA 16
#define THREADS 480                       // 15 warps
#define ROWS_PER_CTA  (WORDS_PER_CTA * M_OUT)          // 160
#define VEC_PER_CTA   (WORDS_PER_CTA * M_OUT * D_VEC)  // 12000 = 25 * 480

__global__ __launch_bounds__(THREADS, 4)
void word_embed_kernel(const float* __restrict__ emb_table,   // [36, 300]
                       const float* __restrict__ pad_table,   // [1, 300]
                       const int*   __restrict__ tokens,      // [B, 24]
                       const int*   __restrict__ lengths,     // [B]
                       float*       __restrict__ out)         // [B, 10, 300]
{
    const int word_base = blockIdx.x * WORDS_PER_CTA;
    const int tid = threadIdx.x;

    // Per-row metadata: {lo_vec_off (int bits), hi_vec_off (int bits), w, 1-w}
    // lo_vec_off = token_lo * 75 (float4 index into emb table); -1 => pad row.
    __shared__ float4 s_meta[ROWS_PER_CTA];

    if (tid < ROWS_PER_CTA) {
        const int wrd = tid / M_OUT;          // 0..15
        const int m   = tid - wrd * M_OUT;    // 0..9
        const int b   = word_base + wrd;
        const int L   = __ldg(lengths + b);
        int   lo75, hi75;
        float w;
        if (L < M_OUT) {
            if (m < L) {
                lo75 = __ldg(tokens + b * LMAX + m) * D_VEC;
            } else {
                lo75 = -1;   // pad row
            }
            hi75 = lo75;
            w    = 0.0f;
        } else {
            // pos = m * (L-1) / (M-1), fp32 exactly as the reference
            const float pos = (float)m * (float)(L - 1) / 9.0f;
            int lo = (int)floorf(pos);
            int hi = min(lo + 1, L - 1);
            w    = pos - (float)lo;
            lo75 = __ldg(tokens + b * LMAX + lo) * D_VEC;
            hi75 = (w != 0.0f) ? __ldg(tokens + b * LMAX + hi) * D_VEC : lo75;
        }
        s_meta[tid] = make_float4(__int_as_float(lo75), __int_as_float(hi75),
                                  w, 1.0f - w);
    }
    __syncthreads();

    const float4* __restrict__ embv = (const float4*)emb_table;  // [36, 75]
    const float4* __restrict__ padv = (const float4*)pad_table;  // [75]
    float4* __restrict__ outv = (float4*)out + (size_t)word_base * (M_OUT * D_VEC);

    #pragma unroll 5
    for (int k = 0; k < VEC_PER_CTA / THREADS; k++) {    // 25 uniform iterations
        const int idx  = tid + k * THREADS;
        const int row  = idx / D_VEC;          // 0..159 (const-div)
        const int d4   = idx - row * D_VEC;

        const float4 meta = s_meta[row];       // one LDS.128 (warp-broadcast)
        const int lo75 = __float_as_int(meta.x);

        float4 r;
        if (lo75 < 0) {
            r = __ldg(padv + d4);                        // pad row (L1 hit)
        } else {
            const float4 a = __ldg(embv + lo75 + d4);    // L1 hit
            r = a;
            const float w = meta.z;
            if (w != 0.0f) {                             // ~50% of elements
                const int hi75 = __float_as_int(meta.y);
                const float4 c = __ldg(embv + hi75 + d4);
                const float iw = meta.w;
                r.x = a.x * iw + c.x * w;
                r.y = a.y * iw + c.y * w;
                r.z = a.z * iw + c.z * w;
                r.w = a.w * iw + c.w * w;
            }
        }
        __stcs(outv + idx, r);   // streaming store: write-once, evict-first
    }
}

extern "C" void kernel_launch(void* const* d_in, const int* in_sizes, int n_in,
                              void* d_out, int out_size)
{
    const float* emb_table = (const float*)d_in[0];  // [36, 300] f32
    const float* pad_table = (const float*)d_in[1];  // [1, 300]  f32
    const int*   tokens    = (const int*)  d_in[2];  // [32768, 24] i32
    const int*   lengths   = (const int*)  d_in[3];  // [32768]     i32
    float*       out       = (float*)d_out;          // [32768, 10, 300] f32

    word_embed_kernel<<<B_WORDS / WORDS_PER_CTA, THREADS>>>(
        emb_table, pad_table, tokens, lengths, out);
}